// round 17
// baseline (speedup 1.0000x reference)
#include <cuda_runtime.h>
#include <cuda_bf16.h>

// SE block: B=32, H=W=56 (HW=3136), C=256, R=16
#define HW      3136
#define CCH     256
#define NB      32
#define RPU     8                   // rows per warp-unit
#define UPB     (HW / RPU)          // 392 units per batch
#define NUNITW  (NB * UPB)          // 12544 warp-units
#define NBLK    592                 // 148 SMs * 4, co-resident (champion config)
#define NWARP   (NBLK * 8)          // 4736 warps
#define KTICK   (NUNITW + NWARP)    // 17280 draws per phase, exact (work + exit draws)

// Scratch (__device__ globals per allocation-free rule)
__device__ float g_partial[NUNITW * CCH];  // [u][c]  (12.8 MB)
__device__ float g_gate[NB * CCH];
__device__ unsigned g_tick1 = 0;           // phase-1 warp tickets (never reset; modulo KTICK)
__device__ unsigned g_tick2 = 0;           // phase-2 warp tickets
__device__ unsigned g_count = 0;           // barrier arrivals (self-resetting)
__device__ unsigned g_gen   = 0;           // barrier generation (monotonic)

__device__ __forceinline__ void grid_barrier() {
    __syncthreads();
    if (threadIdx.x == 0) {
        unsigned gen = *((volatile unsigned*)&g_gen);
        __threadfence();
        if (atomicAdd(&g_count, 1u) == NBLK - 1) {
            g_count = 0;
            __threadfence();
            atomicAdd(&g_gen, 1u);
        } else {
            while (*((volatile unsigned*)&g_gen) == gen) { }
        }
        __threadfence();
    }
    __syncthreads();
}

// Warp-uniform ticket draw: lane0 atomics, broadcast via shfl. Valid iff < NUNITW.
__device__ __forceinline__ int warp_ticket(unsigned* ctr, int lane) {
    unsigned raw = 0;
    if (lane == 0) raw = atomicAdd(ctr, 1u) % KTICK;
    return (int)__shfl_sync(0xFFFFFFFFu, raw, 0);
}

__global__ void __launch_bounds__(256, 4)
k_se(const float* __restrict__ x,
     const float* __restrict__ w1,
     const float* __restrict__ b1,
     const float* __restrict__ w2,
     const float* __restrict__ b2,
     float* __restrict__ out) {
    const int bid  = blockIdx.x;
    const int t    = threadIdx.x;
    const int lane = t & 31;

    const float4* x4 = reinterpret_cast<const float4*>(x);
    float4*       o4 = reinterpret_cast<float4*>(out);
    float4*       p4 = reinterpret_cast<float4*>(g_partial);

    // ---------------- Phase 1: warp-autonomous pooling (no block syncs) ----------------
    for (;;) {
        const int u = warp_ticket(&g_tick1, lane);
        if (u >= NUNITW) break;
        // unit u: rows u*8 .. u*8+7 (never crosses a batch); lane owns c4 = lane, lane+32
        const size_t rbase = (size_t)u * RPU * (CCH / 4);

        float4 s0 = make_float4(0.f, 0.f, 0.f, 0.f);
        float4 s1 = make_float4(0.f, 0.f, 0.f, 0.f);
#pragma unroll
        for (int k = 0; k < RPU; k++) {
            float4 a = x4[rbase + (size_t)k * (CCH / 4) + lane];
            float4 c = x4[rbase + (size_t)k * (CCH / 4) + lane + 32];
            s0.x += a.x; s0.y += a.y; s0.z += a.z; s0.w += a.w;
            s1.x += c.x; s1.y += c.y; s1.z += c.z; s1.w += c.w;
        }
        p4[(size_t)u * (CCH / 4) + lane]      = s0;
        p4[(size_t)u * (CCH / 4) + lane + 32] = s1;
        // publication: grid barrier below (no per-unit fence — R15 lesson)
    }

    grid_barrier();

    // ---------------- Phase MLP: blocks 0..31, one per batch ----------------
    if (bid < NB) {
        const int b = bid;
        __shared__ float s_s[CCH];
        __shared__ float s_h[16];
        __shared__ float s_w1[CCH * 16];
        __shared__ float s_p[256];

#pragma unroll
        for (int i = t; i < CCH * 16; i += 256) s_w1[i] = w1[i];

        float accm = 0.f;
        const float* pb = g_partial + (size_t)b * UPB * CCH + t;
#pragma unroll 8
        for (int ss = 0; ss < UPB; ss++)
            accm += __ldcg(pb + (size_t)ss * CCH);
        s_s[t] = accm * (1.0f / (float)HW);
        __syncthreads();

        {   // dense1 parallelized: t = grp*16 + cout
            const int cout = t & 15;
            const int grp  = t >> 4;
            float p = 0.f;
#pragma unroll
            for (int k = grp * 16; k < grp * 16 + 16; k++)
                p = fmaf(s_s[k], s_w1[k * 16 + cout], p);
            s_p[t] = p;
        }
        __syncthreads();
        if (t < 16) {
            float h = b1[t];
#pragma unroll
            for (int j = 0; j < 16; j++)
                h += s_p[j * 16 + t];
            s_h[t] = fmaxf(h, 0.f);
        }
        __syncthreads();

        float g = b2[t];
#pragma unroll
        for (int j = 0; j < 16; j++)
            g = fmaf(s_h[j], w2[j * CCH + t], g);
        g_gate[b * CCH + t] = 1.f / (1.f + __expf(-g));
    }

    grid_barrier();

    // ------------- Phase 2: warp-autonomous scale, reverse recency (no block syncs) -------------
    for (;;) {
        const int v = warp_ticket(&g_tick2, lane);
        if (v >= NUNITW) break;
        const int u = NUNITW - 1 - v;          // most-recently-pooled first (L2-hot)
        const int b = u / UPB;
        const size_t rbase = (size_t)u * RPU * (CCH / 4);

        const float4 ga = reinterpret_cast<const float4*>(g_gate)[b * (CCH / 4) + lane];
        const float4 gc = reinterpret_cast<const float4*>(g_gate)[b * (CCH / 4) + lane + 32];

#pragma unroll
        for (int k = 0; k < RPU; k++) {
            const size_t ia = rbase + (size_t)k * (CCH / 4) + lane;
            const size_t ic = ia + 32;
            float4 a = x4[ia];
            float4 c = x4[ic];
            a.x *= ga.x; a.y *= ga.y; a.z *= ga.z; a.w *= ga.w;
            c.x *= gc.x; c.y *= gc.y; c.z *= gc.z; c.w *= gc.w;
            o4[ia] = a;                        // write-back: lazy DRAM drain (R11 win)
            o4[ic] = c;
        }
    }
}

extern "C" void kernel_launch(void* const* d_in, const int* in_sizes, int n_in,
                              void* d_out, int out_size) {
    const float* x  = (const float*)d_in[0];
    const float* w1 = (const float*)d_in[1];
    const float* b1 = (const float*)d_in[2];
    const float* w2 = (const float*)d_in[3];
    const float* b2 = (const float*)d_in[4];
    float* out = (float*)d_out;

    k_se<<<NBLK, 256>>>(x, w1, b1, w2, b2, out);
}